// round 14
// baseline (speedup 1.0000x reference)
#include <cuda_runtime.h>
#include <cuda_fp16.h>
#include <cuda_bf16.h>
#include <cstdint>

#define N_NODES 50000
#define N_EDGES 1600000
#define IN_F    256
#define OUT_F   128
#define NEG_SLOPE 0.2f

#define GEMM_BLOCKS ((N_NODES + 127) / 128)   // 391
#define SCAN_BLOCKS ((N_NODES + 1023) / 1024) // 49

#define PAD 24   // bf16 units per smem row (48B): conflict-free, 16B-aligned rows

// ---------------- scratch (static device globals) -------------------------
__device__ __half g_h[(size_t)N_NODES * OUT_F];   // 12.8 MB, fp16
__device__ float  g_el[N_NODES];
__device__ float  g_er[N_NODES];
__device__ float  g_m[N_NODES];
__device__ float  g_inv[N_NODES];
__device__ float  g_wl[IN_F];
__device__ float  g_wr[IN_F];
__device__ int    g_deg[N_NODES];
__device__ int    g_off[N_NODES + 1];
__device__ int    g_rank[N_EDGES];
__device__ int    g_esrc[N_EDGES];                // src ids, dst-sorted
__device__ int    g_bsum[64];

// ---------------- helpers ----------------------------------------------------
__device__ __forceinline__ uint32_t smem_u32(const void* p) {
    uint32_t a;
    asm("{ .reg .u64 t; cvta.to.shared.u64 t, %1; cvt.u32.u64 %0, t; }" : "=r"(a) : "l"(p));
    return a;
}
__device__ __forceinline__ void ldsm_x4(uint32_t* r, uint32_t addr) {
    asm volatile("ldmatrix.sync.aligned.m8n8.x4.shared.b16 {%0,%1,%2,%3}, [%4];"
        : "=r"(r[0]), "=r"(r[1]), "=r"(r[2]), "=r"(r[3]) : "r"(addr));
}
__device__ __forceinline__ void ldsm_x2(uint32_t* r, uint32_t addr) {
    asm volatile("ldmatrix.sync.aligned.m8n8.x2.shared.b16 {%0,%1}, [%2];"
        : "=r"(r[0]), "=r"(r[1]) : "r"(addr));
}
__device__ __forceinline__ void mma_bf16(float* c, const uint32_t* a, const uint32_t* b) {
    asm volatile(
        "mma.sync.aligned.m16n8k16.row.col.f32.bf16.bf16.f32 "
        "{%0,%1,%2,%3}, {%4,%5,%6,%7}, {%8,%9}, {%0,%1,%2,%3};"
        : "+f"(c[0]), "+f"(c[1]), "+f"(c[2]), "+f"(c[3])
        : "r"(a[0]), "r"(a[1]), "r"(a[2]), "r"(a[3]), "r"(b[0]), "r"(b[1]));
}

__device__ __forceinline__ void split_bf16(float4 v, uint2& hi, uint2& lo) {
    __nv_bfloat162 h01 = __floats2bfloat162_rn(v.x, v.y);
    __nv_bfloat162 h23 = __floats2bfloat162_rn(v.z, v.w);
    float2 f01 = __bfloat1622float2(h01);
    float2 f23 = __bfloat1622float2(h23);
    __nv_bfloat162 l01 = __floats2bfloat162_rn(v.x - f01.x, v.y - f01.y);
    __nv_bfloat162 l23 = __floats2bfloat162_rn(v.z - f23.x, v.w - f23.y);
    hi.x = *(unsigned*)&h01; hi.y = *(unsigned*)&h23;
    lo.x = *(unsigned*)&l01; lo.y = *(unsigned*)&l23;
}

// ---------------- 1a) gemm via mma.sync bf16 3-split + ldmatrix ------------
__global__ __launch_bounds__(256, 2) void gemm_kernel(
        const float* __restrict__ feat,
        const float* __restrict__ W) {
    __shared__ __nv_bfloat16 Ah[2][128 * PAD], Al[2][128 * PAD];
    __shared__ __nv_bfloat16 Bh[2][128 * PAD], Bl[2][128 * PAD];

    int tid  = threadIdx.x;
    int wid  = tid >> 5, lane = tid & 31;
    int wr   = wid >> 2;
    int wc   = wid & 3;
    int g    = lane >> 2;
    int c0   = (lane & 3) * 2;
    int row0 = blockIdx.x * 128;

    const uint32_t uAh = smem_u32(Ah), uAl = smem_u32(Al);
    const uint32_t uBh = smem_u32(Bh), uBl = smem_u32(Bl);
    const uint32_t BUFB = 128 * PAD * 2;

    int lrow = lane & 7;
    uint32_t laneA_off = ((lrow + ((lane >> 3) & 1) * 8) * PAD + (lane >> 4) * 8) * 2;
    uint32_t laneB_off = (lrow * PAD + ((lane >> 3) & 1) * 8) * 2;

    float acc[4][4][4];
#pragma unroll
    for (int i = 0; i < 4; i++)
#pragma unroll
        for (int j = 0; j < 4; j++)
#pragma unroll
            for (int k = 0; k < 4; k++) acc[i][j][k] = 0.f;

    int idx0 = tid * 2, idx1 = tid * 2 + 1;
    int lr0 = idx0 >> 2, lq0 = (idx0 & 3) * 4;
    int lr1 = idx1 >> 2, lq1 = (idx1 & 3) * 4;
    bool v0 = (row0 + lr0) < N_NODES;
    bool v1 = (row0 + lr1) < N_NODES;
    const float* pA0 = &feat[(size_t)(row0 + lr0) * IN_F + lq0];
    const float* pA1 = &feat[(size_t)(row0 + lr1) * IN_F + lq1];
    const float* pB0 = &W[(size_t)lr0 * IN_F + lq0];
    const float* pB1 = &W[(size_t)lr1 * IN_F + lq1];

    float4 fa0 = make_float4(0.f, 0.f, 0.f, 0.f), fa1 = fa0, fw0, fw1;
    if (v0) fa0 = *(const float4*)pA0;
    if (v1) fa1 = *(const float4*)pA1;
    fw0 = *(const float4*)pB0;
    fw1 = *(const float4*)pB1;

    {
        uint2 hi, lo;
        split_bf16(fa0, hi, lo);
        *(uint2*)&Ah[0][lr0 * PAD + lq0] = hi; *(uint2*)&Al[0][lr0 * PAD + lq0] = lo;
        split_bf16(fa1, hi, lo);
        *(uint2*)&Ah[0][lr1 * PAD + lq1] = hi; *(uint2*)&Al[0][lr1 * PAD + lq1] = lo;
        split_bf16(fw0, hi, lo);
        *(uint2*)&Bh[0][lr0 * PAD + lq0] = hi; *(uint2*)&Bl[0][lr0 * PAD + lq0] = lo;
        split_bf16(fw1, hi, lo);
        *(uint2*)&Bh[0][lr1 * PAD + lq1] = hi; *(uint2*)&Bl[0][lr1 * PAD + lq1] = lo;
    }
    __syncthreads();

    int buf = 0;
#pragma unroll 1
    for (int ch = 0; ch < IN_F / 16; ch++) {
        if (ch + 1 < IN_F / 16) {
            int kk = (ch + 1) * 16;
            fa0 = make_float4(0.f, 0.f, 0.f, 0.f); fa1 = fa0;
            if (v0) fa0 = *(const float4*)(pA0 + kk);
            if (v1) fa1 = *(const float4*)(pA1 + kk);
            fw0 = *(const float4*)(pB0 + kk);
            fw1 = *(const float4*)(pB1 + kk);
        }

#pragma unroll
        for (int s = 0; s < 3; s++) {
            uint32_t uA = ((s == 2) ? uAl : uAh) + buf * BUFB;
            uint32_t uB = ((s == 1) ? uBl : uBh) + buf * BUFB;
            uint32_t a[4][4], b[4][2];
#pragma unroll
            for (int mt = 0; mt < 4; mt++) {
                uint32_t addr = uA + (uint32_t)(wr * 64 + mt * 16) * (PAD * 2) + laneA_off;
                ldsm_x4(a[mt], addr);
            }
#pragma unroll
            for (int nt = 0; nt < 4; nt++) {
                uint32_t addr = uB + (uint32_t)(wc * 32 + nt * 8) * (PAD * 2) + laneB_off;
                ldsm_x2(b[nt], addr);
            }
#pragma unroll
            for (int mt = 0; mt < 4; mt++)
#pragma unroll
                for (int nt = 0; nt < 4; nt++)
                    mma_bf16(acc[mt][nt], a[mt], b[nt]);
        }

        if (ch + 1 < IN_F / 16) {
            int nb = buf ^ 1;
            uint2 hi, lo;
            split_bf16(fa0, hi, lo);
            *(uint2*)&Ah[nb][lr0 * PAD + lq0] = hi; *(uint2*)&Al[nb][lr0 * PAD + lq0] = lo;
            split_bf16(fa1, hi, lo);
            *(uint2*)&Ah[nb][lr1 * PAD + lq1] = hi; *(uint2*)&Al[nb][lr1 * PAD + lq1] = lo;
            split_bf16(fw0, hi, lo);
            *(uint2*)&Bh[nb][lr0 * PAD + lq0] = hi; *(uint2*)&Bl[nb][lr0 * PAD + lq0] = lo;
            split_bf16(fw1, hi, lo);
            *(uint2*)&Bh[nb][lr1 * PAD + lq1] = hi; *(uint2*)&Bl[nb][lr1 * PAD + lq1] = lo;
            __syncthreads();
            buf = nb;
        }
    }

    // ---- epilogue: store fp16 h only ----
#pragma unroll
    for (int mt = 0; mt < 4; mt++) {
        int r0 = wr * 64 + mt * 16 + g;
        int r1 = r0 + 8;
        int n0 = row0 + r0, n1 = row0 + r1;
#pragma unroll
        for (int nt = 0; nt < 4; nt++) {
            int c = wc * 32 + nt * 8 + c0;
            if (n0 < N_NODES) {
                __half2 p = __floats2half2_rn(acc[mt][nt][0], acc[mt][nt][1]);
                *(unsigned*)&g_h[(size_t)n0 * OUT_F + c] = *(unsigned*)&p;
            }
            if (n1 < N_NODES) {
                __half2 p = __floats2half2_rn(acc[mt][nt][2], acc[mt][nt][3]);
                *(unsigned*)&g_h[(size_t)n1 * OUT_F + c] = *(unsigned*)&p;
            }
        }
    }
}

// ---------------- 1b) projected attention vectors: w_l = W^T attn_l --------
__global__ void wlr_kernel(const float* __restrict__ W,
                           const float* __restrict__ attn_l,
                           const float* __restrict__ attn_r) {
    int k = threadIdx.x;                   // 256 threads
    float sl = 0.f, sr = 0.f;
    for (int d = 0; d < OUT_F; d++) {
        float w = W[(size_t)d * IN_F + k];
        sl += attn_l[d] * w;
        sr += attn_r[d] * w;
    }
    g_wl[k] = sl; g_wr[k] = sr;
}

// ---------------- 1c) el/er = feat . w_{l,r}  (one warp per node) ----------
__global__ __launch_bounds__(256) void eler_kernel(const float* __restrict__ feat) {
    __shared__ float swl[IN_F], swr[IN_F];
    int tid = threadIdx.x;
    if (tid < IN_F) { swl[tid] = g_wl[tid]; swr[tid] = g_wr[tid]; }
    __syncthreads();
    int warp = tid >> 5, lane = tid & 31;
    int node = blockIdx.x * 8 + warp;
    if (node >= N_NODES) return;
    const float* row = &feat[(size_t)node * IN_F + lane * 8];
    float4 f0 = *(const float4*)row;
    float4 f1 = *(const float4*)(row + 4);
    const float* wl = &swl[lane * 8];
    const float* wr = &swr[lane * 8];
    float sl = f0.x*wl[0] + f0.y*wl[1] + f0.z*wl[2] + f0.w*wl[3]
             + f1.x*wl[4] + f1.y*wl[5] + f1.z*wl[6] + f1.w*wl[7];
    float sr = f0.x*wr[0] + f0.y*wr[1] + f0.z*wr[2] + f0.w*wr[3]
             + f1.x*wr[4] + f1.y*wr[5] + f1.z*wr[6] + f1.w*wr[7];
#pragma unroll
    for (int d = 16; d; d >>= 1) {
        sl += __shfl_xor_sync(0xffffffffu, sl, d);
        sr += __shfl_xor_sync(0xffffffffu, sr, d);
    }
    if (lane == 0) { g_el[node] = sl; g_er[node] = sr; }
}

// ---------------- 1d) hist: dst histogram + per-edge rank ------------------
__global__ void hist_kernel(const int* __restrict__ dst) {
    int i = blockIdx.x * blockDim.x + threadIdx.x;
    const int n4 = N_EDGES / 4;
    if (i >= n4) return;
    int4 v = ((const int4*)dst)[i];
    int4 r;
    r.x = atomicAdd(&g_deg[v.x], 1);
    r.y = atomicAdd(&g_deg[v.y], 1);
    r.z = atomicAdd(&g_deg[v.z], 1);
    r.w = atomicAdd(&g_deg[v.w], 1);
    ((int4*)g_rank)[i] = r;
}

// ---------------- 2) scan stage 1 -------------------------------------------
__global__ __launch_bounds__(1024) void scan1_kernel() {
    __shared__ int ws[32];
    int tid = threadIdx.x, lane = tid & 31, warp = tid >> 5;
    int idx = blockIdx.x * 1024 + tid;
    int v = (idx < N_NODES) ? g_deg[idx] : 0;
    int s = v;
#pragma unroll
    for (int d = 16; d; d >>= 1) s += __shfl_xor_sync(0xffffffffu, s, d);
    if (lane == 0) ws[warp] = s;
    __syncthreads();
    if (warp == 0) {
        int t = ws[lane];
#pragma unroll
        for (int d = 16; d; d >>= 1) t += __shfl_xor_sync(0xffffffffu, t, d);
        if (lane == 0) g_bsum[blockIdx.x] = t;
    }
}

// ---------------- scan stages 2+3 merged ------------------------------------
__global__ __launch_bounds__(1024) void scan23_kernel() {
    __shared__ int ws[32];
    __shared__ int blk_pref[64];
    int tid = threadIdx.x, lane = tid & 31, warp = tid >> 5;

    if (warp < 2) {
        int i = tid;
        int v = (i < SCAN_BLOCKS) ? g_bsum[i] : 0;
        int incl = v;
#pragma unroll
        for (int d = 1; d < 32; d <<= 1) {
            int t = __shfl_up_sync(0xffffffffu, incl, d);
            if (lane >= d) incl += t;
        }
        blk_pref[i] = incl - v;
    }
    __syncthreads();
    if (tid == 32) {
        int w0 = blk_pref[31] + g_bsum[31];
        for (int i = 32; i < 64; i++) blk_pref[i] += w0;
    }
    __syncthreads();

    int idx = blockIdx.x * 1024 + tid;
    int v = (idx < N_NODES) ? g_deg[idx] : 0;
    int incl = v;
#pragma unroll
    for (int d = 1; d < 32; d <<= 1) {
        int t = __shfl_up_sync(0xffffffffu, incl, d);
        if (lane >= d) incl += t;
    }
    if (lane == 31) ws[warp] = incl;
    __syncthreads();
    if (warp == 0) {
        int t = ws[lane];
#pragma unroll
        for (int d = 1; d < 32; d <<= 1) {
            int u = __shfl_up_sync(0xffffffffu, t, d);
            if (lane >= d) t += u;
        }
        ws[lane] = t;
    }
    __syncthreads();
    int excl = blk_pref[blockIdx.x] + ((warp > 0) ? ws[warp - 1] : 0) + incl - v;
    if (idx < N_NODES) g_off[idx] = excl;
    if (idx == N_NODES - 1) g_off[N_NODES] = N_EDGES;
}

// ---------------- 3) scatter src only ---------------------------------------
__global__ void scatter_kernel(const int* __restrict__ src,
                               const int* __restrict__ dst) {
    int i = blockIdx.x * blockDim.x + threadIdx.x;
    const int n4 = N_EDGES / 4;
    if (i >= n4) return;
    int4 s4 = ((const int4*)src)[i];
    int4 d4 = ((const int4*)dst)[i];
    int4 r4 = ((const int4*)g_rank)[i];
#pragma unroll
    for (int q = 0; q < 4; q++) {
        int s = (q == 0) ? s4.x : (q == 1) ? s4.y : (q == 2) ? s4.z : s4.w;
        int d = (q == 0) ? d4.x : (q == 1) ? d4.y : (q == 2) ? d4.z : d4.w;
        int r = (q == 0) ? r4.x : (q == 1) ? r4.y : (q == 2) ? r4.z : r4.w;
        g_esrc[g_off[d] + r] = s;
    }
}

// ---------------- 3b) softmax stats per node (stream B, hidden) ------------
__global__ void stats_kernel() {
    int w    = (blockIdx.x * blockDim.x + threadIdx.x) >> 5;
    int lane = threadIdx.x & 31;
    if (w >= N_NODES) return;
    int beg = g_off[w], end = g_off[w + 1];
    float erv = g_er[w];
    float m = -3.402823466e38f, s = 0.f;
    for (int i = beg + lane; i < end; i += 32) {
        float e = g_el[g_esrc[i]] + erv;
        e = (e > 0.f) ? e : NEG_SLOPE * e;
        float mn = fmaxf(m, e);
        s = s * __expf(m - mn) + __expf(e - mn);
        m = mn;
    }
#pragma unroll
    for (int d = 16; d; d >>= 1) {
        float m2 = __shfl_xor_sync(0xffffffffu, m, d);
        float s2 = __shfl_xor_sync(0xffffffffu, s, d);
        float mn = fmaxf(m, m2);
        s = s * __expf(m - mn) + s2 * __expf(m2 - mn);
        m = mn;
    }
    if (lane == 0) {
        g_m[w] = m;
        g_inv[w] = 1.f / fmaxf(s, 1e-9f);
    }
}

// ---------------- 4) aggregation (pass 2 only), one warp per dst node ------
__device__ __forceinline__ void fma_h(float4& acc, float aa, unsigned ss, int lane) {
    uint2 u = *(const uint2*)&g_h[(size_t)ss * OUT_F + lane * 4];
    float2 f0 = __half22float2(*(__half2*)&u.x);
    float2 f1 = __half22float2(*(__half2*)&u.y);
    acc.x += aa * f0.x; acc.y += aa * f0.y;
    acc.z += aa * f1.x; acc.w += aa * f1.y;
}

__global__ void agg_kernel(float* __restrict__ out) {
    int w    = (blockIdx.x * blockDim.x + threadIdx.x) >> 5;
    int lane = threadIdx.x & 31;
    if (w >= N_NODES) return;

    int beg = g_off[w], end = g_off[w + 1];
    float erv = g_er[w];
    float m   = g_m[w];
    float inv = g_inv[w];

    float4 acc = make_float4(0.f, 0.f, 0.f, 0.f);
    for (int j0 = beg; j0 < end; j0 += 32) {
        int myj = j0 + lane;
        int sidx = 0; float a = 0.f;
        if (myj < end) {
            sidx = g_esrc[myj];
            float e = g_el[sidx] + erv;
            e = (e > 0.f) ? e : NEG_SLOPE * e;
            a = __expf(e - m) * inv;
        }
        int cnt = min(32, end - j0);
        int t = 0;
        for (; t + 4 <= cnt; t += 4) {
            int   ss0 = __shfl_sync(0xffffffffu, sidx, t + 0);
            int   ss1 = __shfl_sync(0xffffffffu, sidx, t + 1);
            int   ss2 = __shfl_sync(0xffffffffu, sidx, t + 2);
            int   ss3 = __shfl_sync(0xffffffffu, sidx, t + 3);
            float a0 = __shfl_sync(0xffffffffu, a, t + 0);
            float a1 = __shfl_sync(0xffffffffu, a, t + 1);
            float a2 = __shfl_sync(0xffffffffu, a, t + 2);
            float a3 = __shfl_sync(0xffffffffu, a, t + 3);
            uint2 u0 = *(const uint2*)&g_h[(size_t)ss0 * OUT_F + lane * 4];
            uint2 u1 = *(const uint2*)&g_h[(size_t)ss1 * OUT_F + lane * 4];
            uint2 u2 = *(const uint2*)&g_h[(size_t)ss2 * OUT_F + lane * 4];
            uint2 u3 = *(const uint2*)&g_h[(size_t)ss3 * OUT_F + lane * 4];
            float2 f;
            f = __half22float2(*(__half2*)&u0.x); acc.x += a0 * f.x; acc.y += a0 * f.y;
            f = __half22float2(*(__half2*)&u0.y); acc.z += a0 * f.x; acc.w += a0 * f.y;
            f = __half22float2(*(__half2*)&u1.x); acc.x += a1 * f.x; acc.y += a1 * f.y;
            f = __half22float2(*(__half2*)&u1.y); acc.z += a1 * f.x; acc.w += a1 * f.y;
            f = __half22float2(*(__half2*)&u2.x); acc.x += a2 * f.x; acc.y += a2 * f.y;
            f = __half22float2(*(__half2*)&u2.y); acc.z += a2 * f.x; acc.w += a2 * f.y;
            f = __half22float2(*(__half2*)&u3.x); acc.x += a3 * f.x; acc.y += a3 * f.y;
            f = __half22float2(*(__half2*)&u3.y); acc.z += a3 * f.x; acc.w += a3 * f.y;
        }
        for (; t < cnt; t++) {
            int   ss = __shfl_sync(0xffffffffu, sidx, t);
            float aa = __shfl_sync(0xffffffffu, a, t);
            fma_h(acc, aa, ss, lane);
        }
    }
    *(float4*)&out[(size_t)w * OUT_F + lane * 4] = acc;
}

// ---------------- launch: forked-stream graph -------------------------------
extern "C" void kernel_launch(void* const* d_in, const int* in_sizes, int n_in,
                              void* d_out, int out_size) {
    const float* feat   = (const float*)d_in[0];
    const float* W      = (const float*)d_in[1];
    const float* attn_l = (const float*)d_in[2];
    const float* attn_r = (const float*)d_in[3];
    const int*   src    = (const int*)d_in[4];
    const int*   dst    = (const int*)d_in[5];
    float* out = (float*)d_out;

    static cudaStream_t sB = nullptr;
    static cudaEvent_t evFork = nullptr, evJoin = nullptr;
    if (!sB) {
        cudaStreamCreateWithFlags(&sB, cudaStreamNonBlocking);
        cudaEventCreateWithFlags(&evFork, cudaEventDisableTiming);
        cudaEventCreateWithFlags(&evJoin, cudaEventDisableTiming);
    }

    void* deg_ptr = nullptr;
    cudaGetSymbolAddress(&deg_ptr, g_deg);

    // fork: stream B does everything except the gemm and final agg
    cudaEventRecord(evFork, 0);
    cudaStreamWaitEvent(sB, evFork, 0);
    cudaMemsetAsync(deg_ptr, 0, N_NODES * sizeof(int), sB);
    hist_kernel<<<(N_EDGES / 4 + 255) / 256, 256, 0, sB>>>(dst);
    wlr_kernel<<<1, 256, 0, sB>>>(W, attn_l, attn_r);
    eler_kernel<<<(N_NODES + 7) / 8, 256, 0, sB>>>(feat);
    scan1_kernel<<<SCAN_BLOCKS, 1024, 0, sB>>>();
    scan23_kernel<<<SCAN_BLOCKS, 1024, 0, sB>>>();
    scatter_kernel<<<(N_EDGES / 4 + 255) / 256, 256, 0, sB>>>(src, dst);
    stats_kernel<<<(N_NODES * 32 + 255) / 256, 256, 0, sB>>>();
    cudaEventRecord(evJoin, sB);

    // main stream: gemm concurrently
    gemm_kernel<<<GEMM_BLOCKS, 256>>>(feat, W);

    // join, then agg (pass 2 only)
    cudaStreamWaitEvent(0, evJoin, 0);
    agg_kernel<<<(N_NODES * 32 + 255) / 256, 256>>>(out);
}

// round 15
// speedup vs baseline: 1.1483x; 1.1483x over previous
#include <cuda_runtime.h>
#include <cuda_fp16.h>
#include <cuda_bf16.h>
#include <cstdint>

#define N_NODES 50000
#define N_EDGES 1600000
#define IN_F    256
#define OUT_F   128
#define NEG_SLOPE 0.2f

#define GEMM_BLOCKS ((N_NODES + 127) / 128)   // 391
#define SCAN_BLOCKS ((N_NODES + 1023) / 1024) // 49

#define PAD 24   // bf16 units per smem row (48B): conflict-free, 16B-aligned rows

// ---------------- scratch (static device globals) -------------------------
__device__ __half g_h[(size_t)N_NODES * OUT_F];   // 12.8 MB, fp16
__device__ float  g_el[N_NODES];
__device__ float  g_er[N_NODES];
__device__ int    g_deg[N_NODES];
__device__ int    g_off[N_NODES + 1];
__device__ int    g_rank[N_EDGES];
__device__ int    g_esrc[N_EDGES];                // src ids, dst-sorted
__device__ int    g_bsum[64];

// ---------------- helpers ----------------------------------------------------
__device__ __forceinline__ uint32_t smem_u32(const void* p) {
    uint32_t a;
    asm("{ .reg .u64 t; cvta.to.shared.u64 t, %1; cvt.u32.u64 %0, t; }" : "=r"(a) : "l"(p));
    return a;
}
__device__ __forceinline__ void ldsm_x4(uint32_t* r, uint32_t addr) {
    asm volatile("ldmatrix.sync.aligned.m8n8.x4.shared.b16 {%0,%1,%2,%3}, [%4];"
        : "=r"(r[0]), "=r"(r[1]), "=r"(r[2]), "=r"(r[3]) : "r"(addr));
}
__device__ __forceinline__ void ldsm_x2(uint32_t* r, uint32_t addr) {
    asm volatile("ldmatrix.sync.aligned.m8n8.x2.shared.b16 {%0,%1}, [%2];"
        : "=r"(r[0]), "=r"(r[1]) : "r"(addr));
}
__device__ __forceinline__ void mma_bf16(float* c, const uint32_t* a, const uint32_t* b) {
    asm volatile(
        "mma.sync.aligned.m16n8k16.row.col.f32.bf16.bf16.f32 "
        "{%0,%1,%2,%3}, {%4,%5,%6,%7}, {%8,%9}, {%0,%1,%2,%3};"
        : "+f"(c[0]), "+f"(c[1]), "+f"(c[2]), "+f"(c[3])
        : "r"(a[0]), "r"(a[1]), "r"(a[2]), "r"(a[3]), "r"(b[0]), "r"(b[1]));
}

__device__ __forceinline__ void split_bf16(float4 v, uint2& hi, uint2& lo) {
    __nv_bfloat162 h01 = __floats2bfloat162_rn(v.x, v.y);
    __nv_bfloat162 h23 = __floats2bfloat162_rn(v.z, v.w);
    float2 f01 = __bfloat1622float2(h01);
    float2 f23 = __bfloat1622float2(h23);
    __nv_bfloat162 l01 = __floats2bfloat162_rn(v.x - f01.x, v.y - f01.y);
    __nv_bfloat162 l23 = __floats2bfloat162_rn(v.z - f23.x, v.w - f23.y);
    hi.x = *(unsigned*)&h01; hi.y = *(unsigned*)&h23;
    lo.x = *(unsigned*)&l01; lo.y = *(unsigned*)&l23;
}

// ---------------- 1a) gemm via mma.sync bf16 3-split + ldmatrix ------------
__global__ __launch_bounds__(256, 2) void gemm_kernel(
        const float* __restrict__ feat,
        const float* __restrict__ W,
        const float* __restrict__ attn_l,
        const float* __restrict__ attn_r) {
    __shared__ __nv_bfloat16 Ah[2][128 * PAD], Al[2][128 * PAD];
    __shared__ __nv_bfloat16 Bh[2][128 * PAD], Bl[2][128 * PAD];
    __shared__ float s_el[128], s_er[128];

    int tid  = threadIdx.x;
    int wid  = tid >> 5, lane = tid & 31;
    int wr   = wid >> 2;
    int wc   = wid & 3;
    int g    = lane >> 2;
    int c0   = (lane & 3) * 2;
    int row0 = blockIdx.x * 128;

    const uint32_t uAh = smem_u32(Ah), uAl = smem_u32(Al);
    const uint32_t uBh = smem_u32(Bh), uBl = smem_u32(Bl);
    const uint32_t BUFB = 128 * PAD * 2;

    int lrow = lane & 7;
    uint32_t laneA_off = ((lrow + ((lane >> 3) & 1) * 8) * PAD + (lane >> 4) * 8) * 2;
    uint32_t laneB_off = (lrow * PAD + ((lane >> 3) & 1) * 8) * 2;

    float acc[4][4][4];
#pragma unroll
    for (int i = 0; i < 4; i++)
#pragma unroll
        for (int j = 0; j < 4; j++)
#pragma unroll
            for (int k = 0; k < 4; k++) acc[i][j][k] = 0.f;

    int idx0 = tid * 2, idx1 = tid * 2 + 1;
    int lr0 = idx0 >> 2, lq0 = (idx0 & 3) * 4;
    int lr1 = idx1 >> 2, lq1 = (idx1 & 3) * 4;
    bool v0 = (row0 + lr0) < N_NODES;
    bool v1 = (row0 + lr1) < N_NODES;
    const float* pA0 = &feat[(size_t)(row0 + lr0) * IN_F + lq0];
    const float* pA1 = &feat[(size_t)(row0 + lr1) * IN_F + lq1];
    const float* pB0 = &W[(size_t)lr0 * IN_F + lq0];
    const float* pB1 = &W[(size_t)lr1 * IN_F + lq1];

    float4 fa0 = make_float4(0.f, 0.f, 0.f, 0.f), fa1 = fa0, fw0, fw1;
    if (v0) fa0 = *(const float4*)pA0;
    if (v1) fa1 = *(const float4*)pA1;
    fw0 = *(const float4*)pB0;
    fw1 = *(const float4*)pB1;

    {
        uint2 hi, lo;
        split_bf16(fa0, hi, lo);
        *(uint2*)&Ah[0][lr0 * PAD + lq0] = hi; *(uint2*)&Al[0][lr0 * PAD + lq0] = lo;
        split_bf16(fa1, hi, lo);
        *(uint2*)&Ah[0][lr1 * PAD + lq1] = hi; *(uint2*)&Al[0][lr1 * PAD + lq1] = lo;
        split_bf16(fw0, hi, lo);
        *(uint2*)&Bh[0][lr0 * PAD + lq0] = hi; *(uint2*)&Bl[0][lr0 * PAD + lq0] = lo;
        split_bf16(fw1, hi, lo);
        *(uint2*)&Bh[0][lr1 * PAD + lq1] = hi; *(uint2*)&Bl[0][lr1 * PAD + lq1] = lo;
    }
    __syncthreads();

    int buf = 0;
#pragma unroll 1
    for (int ch = 0; ch < IN_F / 16; ch++) {
        if (ch + 1 < IN_F / 16) {
            int kk = (ch + 1) * 16;
            fa0 = make_float4(0.f, 0.f, 0.f, 0.f); fa1 = fa0;
            if (v0) fa0 = *(const float4*)(pA0 + kk);
            if (v1) fa1 = *(const float4*)(pA1 + kk);
            fw0 = *(const float4*)(pB0 + kk);
            fw1 = *(const float4*)(pB1 + kk);
        }

#pragma unroll
        for (int s = 0; s < 3; s++) {
            uint32_t uA = ((s == 2) ? uAl : uAh) + buf * BUFB;
            uint32_t uB = ((s == 1) ? uBl : uBh) + buf * BUFB;
            uint32_t a[4][4], b[4][2];
#pragma unroll
            for (int mt = 0; mt < 4; mt++) {
                uint32_t addr = uA + (uint32_t)(wr * 64 + mt * 16) * (PAD * 2) + laneA_off;
                ldsm_x4(a[mt], addr);
            }
#pragma unroll
            for (int nt = 0; nt < 4; nt++) {
                uint32_t addr = uB + (uint32_t)(wc * 32 + nt * 8) * (PAD * 2) + laneB_off;
                ldsm_x2(b[nt], addr);
            }
#pragma unroll
            for (int mt = 0; mt < 4; mt++)
#pragma unroll
                for (int nt = 0; nt < 4; nt++)
                    mma_bf16(acc[mt][nt], a[mt], b[nt]);
        }

        if (ch + 1 < IN_F / 16) {
            int nb = buf ^ 1;
            uint2 hi, lo;
            split_bf16(fa0, hi, lo);
            *(uint2*)&Ah[nb][lr0 * PAD + lq0] = hi; *(uint2*)&Al[nb][lr0 * PAD + lq0] = lo;
            split_bf16(fa1, hi, lo);
            *(uint2*)&Ah[nb][lr1 * PAD + lq1] = hi; *(uint2*)&Al[nb][lr1 * PAD + lq1] = lo;
            split_bf16(fw0, hi, lo);
            *(uint2*)&Bh[nb][lr0 * PAD + lq0] = hi; *(uint2*)&Bl[nb][lr0 * PAD + lq0] = lo;
            split_bf16(fw1, hi, lo);
            *(uint2*)&Bh[nb][lr1 * PAD + lq1] = hi; *(uint2*)&Bl[nb][lr1 * PAD + lq1] = lo;
            __syncthreads();
            buf = nb;
        }
    }

    // ---- epilogue: store fp16 h, smem-reduce el/er ----
    if (tid < 128) { s_el[tid] = 0.f; s_er[tid] = 0.f; }
    __syncthreads();

#pragma unroll
    for (int mt = 0; mt < 4; mt++) {
        int r0 = wr * 64 + mt * 16 + g;
        int r1 = r0 + 8;
        int n0 = row0 + r0, n1 = row0 + r1;
        float pl0 = 0.f, pr0 = 0.f, pl1 = 0.f, pr1 = 0.f;
#pragma unroll
        for (int nt = 0; nt < 4; nt++) {
            int c = wc * 32 + nt * 8 + c0;
            float c00 = acc[mt][nt][0], c01 = acc[mt][nt][1];
            float c10 = acc[mt][nt][2], c11 = acc[mt][nt][3];
            if (n0 < N_NODES) {
                __half2 p = __floats2half2_rn(c00, c01);
                *(unsigned*)&g_h[(size_t)n0 * OUT_F + c] = *(unsigned*)&p;
            }
            if (n1 < N_NODES) {
                __half2 p = __floats2half2_rn(c10, c11);
                *(unsigned*)&g_h[(size_t)n1 * OUT_F + c] = *(unsigned*)&p;
            }
            float alc0 = attn_l[c], alc1 = attn_l[c + 1];
            float arc0 = attn_r[c], arc1 = attn_r[c + 1];
            pl0 += c00 * alc0 + c01 * alc1;  pr0 += c00 * arc0 + c01 * arc1;
            pl1 += c10 * alc0 + c11 * alc1;  pr1 += c10 * arc0 + c11 * arc1;
        }
        atomicAdd(&s_el[r0], pl0); atomicAdd(&s_er[r0], pr0);
        atomicAdd(&s_el[r1], pl1); atomicAdd(&s_er[r1], pr1);
    }
    __syncthreads();
    if (tid < 128) {
        int n = row0 + tid;
        if (n < N_NODES) { g_el[n] = s_el[tid]; g_er[n] = s_er[tid]; }
    }
}

// ---------------- 1b) hist: dst histogram + per-edge rank (stream B) -------
__global__ void hist_kernel(const int* __restrict__ dst) {
    int i = blockIdx.x * blockDim.x + threadIdx.x;
    const int n4 = N_EDGES / 4;
    if (i >= n4) return;
    int4 v = ((const int4*)dst)[i];
    int4 r;
    r.x = atomicAdd(&g_deg[v.x], 1);
    r.y = atomicAdd(&g_deg[v.y], 1);
    r.z = atomicAdd(&g_deg[v.z], 1);
    r.w = atomicAdd(&g_deg[v.w], 1);
    ((int4*)g_rank)[i] = r;
}

// ---------------- 2) scan stage 1 -------------------------------------------
__global__ __launch_bounds__(1024) void scan1_kernel() {
    __shared__ int ws[32];
    int tid = threadIdx.x, lane = tid & 31, warp = tid >> 5;
    int idx = blockIdx.x * 1024 + tid;
    int v = (idx < N_NODES) ? g_deg[idx] : 0;
    int s = v;
#pragma unroll
    for (int d = 16; d; d >>= 1) s += __shfl_xor_sync(0xffffffffu, s, d);
    if (lane == 0) ws[warp] = s;
    __syncthreads();
    if (warp == 0) {
        int t = ws[lane];
#pragma unroll
        for (int d = 16; d; d >>= 1) t += __shfl_xor_sync(0xffffffffu, t, d);
        if (lane == 0) g_bsum[blockIdx.x] = t;
    }
}

// ---------------- scan stages 2+3 merged ------------------------------------
__global__ __launch_bounds__(1024) void scan23_kernel() {
    __shared__ int ws[32];
    __shared__ int blk_pref[64];
    int tid = threadIdx.x, lane = tid & 31, warp = tid >> 5;

    if (warp < 2) {
        int i = tid;
        int v = (i < SCAN_BLOCKS) ? g_bsum[i] : 0;
        int incl = v;
#pragma unroll
        for (int d = 1; d < 32; d <<= 1) {
            int t = __shfl_up_sync(0xffffffffu, incl, d);
            if (lane >= d) incl += t;
        }
        blk_pref[i] = incl - v;
    }
    __syncthreads();
    if (tid == 32) {
        int w0 = blk_pref[31] + g_bsum[31];
        for (int i = 32; i < 64; i++) blk_pref[i] += w0;
    }
    __syncthreads();

    int idx = blockIdx.x * 1024 + tid;
    int v = (idx < N_NODES) ? g_deg[idx] : 0;
    int incl = v;
#pragma unroll
    for (int d = 1; d < 32; d <<= 1) {
        int t = __shfl_up_sync(0xffffffffu, incl, d);
        if (lane >= d) incl += t;
    }
    if (lane == 31) ws[warp] = incl;
    __syncthreads();
    if (warp == 0) {
        int t = ws[lane];
#pragma unroll
        for (int d = 1; d < 32; d <<= 1) {
            int u = __shfl_up_sync(0xffffffffu, t, d);
            if (lane >= d) t += u;
        }
        ws[lane] = t;
    }
    __syncthreads();
    int excl = blk_pref[blockIdx.x] + ((warp > 0) ? ws[warp - 1] : 0) + incl - v;
    if (idx < N_NODES) g_off[idx] = excl;
    if (idx == N_NODES - 1) g_off[N_NODES] = N_EDGES;
}

// ---------------- 3) scatter src only (gemm-independent) --------------------
__global__ void scatter_kernel(const int* __restrict__ src,
                               const int* __restrict__ dst) {
    int i = blockIdx.x * blockDim.x + threadIdx.x;
    const int n4 = N_EDGES / 4;
    if (i >= n4) return;
    int4 s4 = ((const int4*)src)[i];
    int4 d4 = ((const int4*)dst)[i];
    int4 r4 = ((const int4*)g_rank)[i];
#pragma unroll
    for (int q = 0; q < 4; q++) {
        int s = (q == 0) ? s4.x : (q == 1) ? s4.y : (q == 2) ? s4.z : s4.w;
        int d = (q == 0) ? d4.x : (q == 1) ? d4.y : (q == 2) ? d4.z : d4.w;
        int r = (q == 0) ? r4.x : (q == 1) ? r4.y : (q == 2) ? r4.z : r4.w;
        g_esrc[g_off[d] + r] = s;
    }
}

// ---------------- 4) fused online-softmax aggregation, 1 warp per node -----
__global__ void agg_kernel(float* __restrict__ out) {
    int w    = (blockIdx.x * blockDim.x + threadIdx.x) >> 5;
    int lane = threadIdx.x & 31;
    if (w >= N_NODES) return;

    int beg = g_off[w], end = g_off[w + 1];
    float erv = g_er[w];

    // single sweep: online max + unnormalized accumulation (flash style)
    float m = -3.402823466e38f;   // warp-uniform running max
    float s = 0.f;                // per-lane partial sum of exp
    float4 acc = make_float4(0.f, 0.f, 0.f, 0.f);

    for (int j0 = beg; j0 < end; j0 += 32) {
        int myj = j0 + lane;
        int sidx = 0;
        float e = -3.402823466e38f;
        if (myj < end) {
            sidx = g_esrc[myj];
            e = g_el[sidx] + erv;
            e = (e > 0.f) ? e : NEG_SLOPE * e;
        }
        // batch max (warp-uniform)
        float bm = e;
#pragma unroll
        for (int d = 16; d; d >>= 1) bm = fmaxf(bm, __shfl_xor_sync(0xffffffffu, bm, d));
        if (bm > m) {
            float c = __expf(m - bm);    // exp(-inf)=0 on first batch
            s *= c;
            acc.x *= c; acc.y *= c; acc.z *= c; acc.w *= c;
            m = bm;
        }
        float a = (myj < end) ? __expf(e - m) : 0.f;
        s += a;

        int cnt = min(32, end - j0);
        int t = 0;
        for (; t + 4 <= cnt; t += 4) {
            int   ss0 = __shfl_sync(0xffffffffu, sidx, t + 0);
            int   ss1 = __shfl_sync(0xffffffffu, sidx, t + 1);
            int   ss2 = __shfl_sync(0xffffffffu, sidx, t + 2);
            int   ss3 = __shfl_sync(0xffffffffu, sidx, t + 3);
            float a0 = __shfl_sync(0xffffffffu, a, t + 0);
            float a1 = __shfl_sync(0xffffffffu, a, t + 1);
            float a2 = __shfl_sync(0xffffffffu, a, t + 2);
            float a3 = __shfl_sync(0xffffffffu, a, t + 3);
            uint2 u0 = *(const uint2*)&g_h[(size_t)ss0 * OUT_F + lane * 4];
            uint2 u1 = *(const uint2*)&g_h[(size_t)ss1 * OUT_F + lane * 4];
            uint2 u2 = *(const uint2*)&g_h[(size_t)ss2 * OUT_F + lane * 4];
            uint2 u3 = *(const uint2*)&g_h[(size_t)ss3 * OUT_F + lane * 4];
            float2 f;
            f = __half22float2(*(__half2*)&u0.x); acc.x += a0 * f.x; acc.y += a0 * f.y;
            f = __half22float2(*(__half2*)&u0.y); acc.z += a0 * f.x; acc.w += a0 * f.y;
            f = __half22float2(*(__half2*)&u1.x); acc.x += a1 * f.x; acc.y += a1 * f.y;
            f = __half22float2(*(__half2*)&u1.y); acc.z += a1 * f.x; acc.w += a1 * f.y;
            f = __half22float2(*(__half2*)&u2.x); acc.x += a2 * f.x; acc.y += a2 * f.y;
            f = __half22float2(*(__half2*)&u2.y); acc.z += a2 * f.x; acc.w += a2 * f.y;
            f = __half22float2(*(__half2*)&u3.x); acc.x += a3 * f.x; acc.y += a3 * f.y;
            f = __half22float2(*(__half2*)&u3.y); acc.z += a3 * f.x; acc.w += a3 * f.y;
        }
        for (; t < cnt; t++) {
            int   ss = __shfl_sync(0xffffffffu, sidx, t);
            float aa = __shfl_sync(0xffffffffu, a, t);
            uint2 u = *(const uint2*)&g_h[(size_t)ss * OUT_F + lane * 4];
            float2 f0 = __half22float2(*(__half2*)&u.x);
            float2 f1 = __half22float2(*(__half2*)&u.y);
            acc.x += aa * f0.x; acc.y += aa * f0.y;
            acc.z += aa * f1.x; acc.w += aa * f1.y;
        }
    }

    // total s across lanes, then normalize
#pragma unroll
    for (int d = 16; d; d >>= 1) s += __shfl_xor_sync(0xffffffffu, s, d);
    float inv = 1.f / fmaxf(s, 1e-9f);
    acc.x *= inv; acc.y *= inv; acc.z *= inv; acc.w *= inv;

    *(float4*)&out[(size_t)w * OUT_F + lane * 4] = acc;
}

// ---------------- launch: forked-stream graph -------------------------------
extern "C" void kernel_launch(void* const* d_in, const int* in_sizes, int n_in,
                              void* d_out, int out_size) {
    const float* feat   = (const float*)d_in[0];
    const float* W      = (const float*)d_in[1];
    const float* attn_l = (const float*)d_in[2];
    const float* attn_r = (const float*)d_in[3];
    const int*   src    = (const int*)d_in[4];
    const int*   dst    = (const int*)d_in[5];
    float* out = (float*)d_out;

    static cudaStream_t sB = nullptr;
    static cudaEvent_t evFork = nullptr, evJoin = nullptr;
    if (!sB) {
        cudaStreamCreateWithFlags(&sB, cudaStreamNonBlocking);
        cudaEventCreateWithFlags(&evFork, cudaEventDisableTiming);
        cudaEventCreateWithFlags(&evJoin, cudaEventDisableTiming);
    }

    void* deg_ptr = nullptr;
    cudaGetSymbolAddress(&deg_ptr, g_deg);

    // fork: stream B does memset -> hist -> scan1 -> scan23 -> scatter
    cudaEventRecord(evFork, 0);
    cudaStreamWaitEvent(sB, evFork, 0);
    cudaMemsetAsync(deg_ptr, 0, N_NODES * sizeof(int), sB);
    hist_kernel<<<(N_EDGES / 4 + 255) / 256, 256, 0, sB>>>(dst);
    scan1_kernel<<<SCAN_BLOCKS, 1024, 0, sB>>>();
    scan23_kernel<<<SCAN_BLOCKS, 1024, 0, sB>>>();
    scatter_kernel<<<(N_EDGES / 4 + 255) / 256, 256, 0, sB>>>(src, dst);
    cudaEventRecord(evJoin, sB);

    // main stream: gemm concurrently
    gemm_kernel<<<GEMM_BLOCKS, 256>>>(feat, W, attn_l, attn_r);

    // join, then fused agg
    cudaStreamWaitEvent(0, evJoin, 0);
    agg_kernel<<<(N_NODES * 32 + 255) / 256, 256>>>(out);
}